// round 15
// baseline (speedup 1.0000x reference)
#include <cuda_runtime.h>
#include <cuda_bf16.h>
#include <cuda_fp16.h>
#include <cstdint>

#define NN 100000
#define EE 1600000
#define NTILES 782          // ceil(NN/128)

// ---------------- scratch (no allocation allowed) ----------------
__device__ __half g_h1[NN * 128];
__device__ __half g_h2[NN * 128];
__device__ float  g_xcomb[NN * 256];
__device__ float  g_as1[NN * 2];
__device__ float  g_ad1[NN * 2];
__device__ float  g_as2[NN * 2];
__device__ float  g_ad2[NN * 2];
__device__ int    g_cnt[2 * NN];
__device__ int    g_offs[2 * (NN + 1)];
__device__ int    g_cur[2 * NN];
__device__ int    g_csr[2 * EE];
// W^T bf16 hi image + lo image (swizzled, chunk-major)
__device__ __align__(16) __nv_bfloat16 g_w1[128 * 512];
__device__ __align__(16) __nv_bfloat16 g_w2[128 * 512];
__device__ __align__(16) __nv_bfloat16 g_wf[64 * 512];

// ---------------- helpers ----------------
__device__ __forceinline__ uint32_t smem_to_u32(const void* p) {
    uint32_t a;
    asm("{ .reg .u64 t; cvta.to.shared.u64 t, %1; cvt.u32.u64 %0, t; }" : "=r"(a) : "l"(p));
    return a;
}
__device__ __forceinline__ void ldmatrix_x4(uint32_t* r, uint32_t addr) {
    asm volatile("ldmatrix.sync.aligned.m8n8.x4.shared.b16 {%0,%1,%2,%3}, [%4];"
        : "=r"(r[0]), "=r"(r[1]), "=r"(r[2]), "=r"(r[3]) : "r"(addr));
}
__device__ __forceinline__ void ldmatrix_x2(uint32_t* r, uint32_t addr) {
    asm volatile("ldmatrix.sync.aligned.m8n8.x2.shared.b16 {%0,%1}, [%2];"
        : "=r"(r[0]), "=r"(r[1]) : "r"(addr));
}
__device__ __forceinline__ void mma16816(float* c, const uint32_t* a, const uint32_t* b) {
    asm volatile(
        "mma.sync.aligned.m16n8k16.row.col.f32.bf16.bf16.f32 "
        "{%0,%1,%2,%3},{%4,%5,%6,%7},{%8,%9},{%0,%1,%2,%3};"
        : "+f"(c[0]), "+f"(c[1]), "+f"(c[2]), "+f"(c[3])
        : "r"(a[0]), "r"(a[1]), "r"(a[2]), "r"(a[3]), "r"(b[0]), "r"(b[1]));
}
__device__ __forceinline__ void cp_async16(uint32_t dst, const void* src) {
    asm volatile("cp.async.cg.shared.global [%0], [%1], 16;" :: "r"(dst), "l"(src));
}
#define CP_COMMIT() asm volatile("cp.async.commit_group;")
#define CP_WAIT(n)  asm volatile("cp.async.wait_group %0;" :: "n"(n))
__device__ __forceinline__ uint32_t bf2bits(__nv_bfloat162 v) {
    return *reinterpret_cast<uint32_t*>(&v);
}
__device__ __forceinline__ uint32_t bfpack(float a, float b) {
    __nv_bfloat162 t = __halves2bfloat162(__float2bfloat16_rn(a), __float2bfloat16_rn(b));
    return *reinterpret_cast<uint32_t*>(&t);
}

// ================= phase1: count edges + prep_w (fused) =================
#define CNT_BLOCKS 12500    // 2*EE / 256
#define PW_BLOCKS 320       // 81920 / 256
#define FILL_BLOCKS 6250    // 2*EE / 512

__global__ __launch_bounds__(256) void phase1_kernel(
    const int* __restrict__ eic, const int* __restrict__ eil,
    const float* __restrict__ W1, const float* __restrict__ W2,
    const float* __restrict__ Wf,
    __nv_bfloat16* __restrict__ o1, __nv_bfloat16* __restrict__ o2,
    __nv_bfloat16* __restrict__ of,
    int* __restrict__ cnt)
{
    const int b = blockIdx.x, tid = threadIdx.x;
    if (b < CNT_BLOCKS) {
        // ---- count incoming edges (both layers) ----
        int j = b * 256 + tid;
        if (j < EE)          atomicAdd(&cnt[eic[EE + j]], 1);
        else                 atomicAdd(&cnt[NN + eil[EE + (j - EE)]], 1);
    } else {
        // ---- prep weights: hi/lo swizzled images ----
        int id = (b - CNT_BLOCKS) * 256 + tid;
        const float* W; __nv_bfloat16* o; int NF, li;
        if (id < 32768)      { W = W1; o = o1; NF = 128; li = id; }
        else if (id < 65536) { W = W2; o = o2; NF = 128; li = id - 32768; }
        else                 { W = Wf; o = of; NF = 64;  li = id - 65536; }
        int n = li % NF, k = li / NF;
        float v = W[li];
        __nv_bfloat16 hv = __float2bfloat16_rn(v);
        __nv_bfloat16 lv = __float2bfloat16_rn(v - __bfloat162float(hv));
        uint32_t off = (uint32_t)((k >> 6) * NF + n) * 128u
                     + (uint32_t)((((k & 63) >> 3) ^ (n & 7)) << 4)
                     + (uint32_t)(k & 7) * 2u;
        *(__nv_bfloat16*)((char*)o + off) = hv;
        *(__nv_bfloat16*)((char*)(o + NF * 256) + off) = lv;
    }
}

// ================= scan (exclusive prefix per layer) =================
__global__ __launch_bounds__(1024) void scan2_kernel(
    const int* __restrict__ cntA, int* __restrict__ offsA, int* __restrict__ curA)
{
    const int L = blockIdx.x;
    const int* cnt = cntA + L * NN;
    int* offs = offsA + L * (NN + 1);
    int* cur  = curA + L * NN;

    __shared__ int sums[1024];
    const int CH = (NN + 1023) / 1024;
    int t = threadIdx.x;
    int base = t * CH;
    int local = 0;
    for (int i = 0; i < CH; i++) {
        int idx = base + i;
        if (idx < NN) local += cnt[idx];
    }
    sums[t] = local;
    __syncthreads();
#pragma unroll
    for (int off = 1; off < 1024; off <<= 1) {
        int v = (t >= off) ? sums[t - off] : 0;
        __syncthreads();
        sums[t] += v;
        __syncthreads();
    }
    int run = sums[t] - local;
    for (int i = 0; i < CH; i++) {
        int idx = base + i;
        if (idx < NN) {
            offs[idx] = run;
            cur[idx] = run;
            run += cnt[idx];
        }
    }
    if (base < NN && base + CH >= NN) offs[NN] = run;
}

// ================= h-GEMM: both layers, inline fp32->bf16 hi/lo split =================
// 148 CTAs: even -> layer1, odd -> layer2 (74 each, strided tiles).
// C = Ahi*Whi + Ahi*Wlo + Alo*Whi, fp32 acc, fp16 output.
__global__ __launch_bounds__(256) void gemm_h_kernel(
    const float* __restrict__ x,
    const __nv_bfloat16* __restrict__ w1, const __nv_bfloat16* __restrict__ w2,
    __half* __restrict__ h1, __half* __restrict__ h2)
{
    constexpr int NT = 8;
    constexpr int OFF_A = 131072;         // after 2 W images (64KB each)

    extern __shared__ __align__(16) char smem[];
    const uint32_t sb = smem_to_u32(smem);
    const int tid = threadIdx.x, wid = tid >> 5, lane = tid & 31;
    const int wm = wid & 3, wn = wid >> 2;
    const int wnb = wn * 64;

    const int half_ = blockIdx.x & 1;
    const int cidx = blockIdx.x >> 1;     // 0..73
    const __nv_bfloat16* Wt = half_ ? w2 : w1;
    __half* H = half_ ? h2 : h1;

    // W images -> smem once
    for (int i = tid; i < 8192; i += 256)
        cp_async16(sb + (uint32_t)i * 16u, ((const uint4*)Wt) + i);
    CP_COMMIT();
    CP_WAIT(0);
    __syncthreads();

    const int r15 = lane & 15, rh = lane >> 4;
    float4 pa[8];

    for (int tile = cidx; tile < NTILES; tile += 74) {
        const int m0 = tile * 128;
        float acc[2][NT][4];
#pragma unroll
        for (int mt = 0; mt < 2; mt++)
#pragma unroll
            for (int nt = 0; nt < NT; nt++)
#pragma unroll
                for (int q = 0; q < 4; q++) acc[mt][nt][q] = 0.f;

        // prefetch chunk 0 (128 rows x 64 fp32)
#pragma unroll
        for (int i = 0; i < 8; i++) {
            int p = i * 256 + tid, row = p >> 4, c4 = p & 15, gm = m0 + row;
            pa[i] = (gm < NN) ? *(const float4*)&x[(size_t)gm * 256 + c4 * 4]
                              : make_float4(0.f, 0.f, 0.f, 0.f);
        }

#pragma unroll
        for (int kc = 0; kc < 4; kc++) {
            const int buf = kc & 1;
            const uint32_t aOff = OFF_A + (uint32_t)buf * 32768u;
            // store A chunk: hi image + lo image, swizzled
#pragma unroll
            for (int i = 0; i < 8; i++) {
                int p = i * 256 + tid, row = p >> 4, c4 = p & 15;
                float4 v = pa[i];
                __nv_bfloat16 h0 = __float2bfloat16_rn(v.x);
                __nv_bfloat16 h1v = __float2bfloat16_rn(v.y);
                __nv_bfloat16 h2v = __float2bfloat16_rn(v.z);
                __nv_bfloat16 h3 = __float2bfloat16_rn(v.w);
                int u = c4 >> 1, hw = (c4 & 1) * 8;
                uint32_t base = (uint32_t)row * 128u +
                                (uint32_t)((u ^ (row & 7)) << 4) + (uint32_t)hw;
                __nv_bfloat162 hp0 = __halves2bfloat162(h0, h1v);
                __nv_bfloat162 hp1 = __halves2bfloat162(h2v, h3);
                *(uint2*)(smem + aOff + base) = make_uint2(bf2bits(hp0), bf2bits(hp1));
                *(uint2*)(smem + aOff + 16384u + base) = make_uint2(
                    bfpack(v.x - __bfloat162float(h0), v.y - __bfloat162float(h1v)),
                    bfpack(v.z - __bfloat162float(h2v), v.w - __bfloat162float(h3)));
            }
            __syncthreads();

            if (kc < 3) {
#pragma unroll
                for (int i = 0; i < 8; i++) {
                    int p = i * 256 + tid, row = p >> 4, c4 = p & 15, gm = m0 + row;
                    pa[i] = (gm < NN)
                        ? *(const float4*)&x[(size_t)gm * 256 + (kc + 1) * 64 + c4 * 4]
                        : make_float4(0.f, 0.f, 0.f, 0.f);
                }
            }

            const uint32_t aH = sb + aOff;
            const uint32_t aL = aH + 16384u;
            const uint32_t bH = sb + (uint32_t)kc * 16384u;
            const uint32_t bL = bH + 65536u;
#pragma unroll
            for (int k16 = 0; k16 < 4; k16++) {
                uint32_t ah[2][4], al[2][4];
#pragma unroll
                for (int mt = 0; mt < 2; mt++) {
                    int row = wm * 32 + mt * 16 + r15;
                    uint32_t off = (uint32_t)row * 128u +
                                   (uint32_t)(((k16 * 2 + rh) ^ (row & 7)) << 4);
                    ldmatrix_x4(ah[mt], aH + off);
                    ldmatrix_x4(al[mt], aL + off);
                }
#pragma unroll
                for (int nt = 0; nt < NT; nt++) {
                    int rn = wnb + nt * 8 + (lane & 7);
                    int un = k16 * 2 + ((lane >> 3) & 1);
                    uint32_t off = (uint32_t)rn * 128u +
                                   (uint32_t)((un ^ (rn & 7)) << 4);
                    uint32_t bh[2], bl[2];
                    ldmatrix_x2(bh, bH + off);
                    ldmatrix_x2(bl, bL + off);
#pragma unroll
                    for (int mt = 0; mt < 2; mt++) {
                        mma16816(acc[mt][nt], ah[mt], bh);
                        mma16816(acc[mt][nt], ah[mt], bl);
                        mma16816(acc[mt][nt], al[mt], bh);
                    }
                }
            }
            __syncthreads();
        }

        // epilogue: fp32 acc -> fp16 stores
#pragma unroll
        for (int nt = 0; nt < NT; nt++) {
            int col = wnb + nt * 8 + (lane & 3) * 2;
#pragma unroll
            for (int mt = 0; mt < 2; mt++) {
                int row = m0 + wm * 32 + mt * 16 + (lane >> 2);
                if (row < NN) {
                    __half2 v = __floats2half2_rn(acc[mt][nt][0], acc[mt][nt][1]);
                    *(__half2*)&H[(size_t)row * 128 + col] = v;
                }
                if (row + 8 < NN) {
                    __half2 v = __floats2half2_rn(acc[mt][nt][2], acc[mt][nt][3]);
                    *(__half2*)&H[(size_t)(row + 8) * 128 + col] = v;
                }
            }
        }
    }
}

// ================= phase3: fill CSR (2 edges/thread) + acoef (fused) =================
__global__ __launch_bounds__(256) void phase3_kernel(
    const int* __restrict__ eic, const int* __restrict__ eil,
    int* __restrict__ cur, int* __restrict__ csr,
    const __half* __restrict__ h1, const __half* __restrict__ h2,
    const float* __restrict__ as1, const float* __restrict__ ad1,
    const float* __restrict__ as2, const float* __restrict__ ad2,
    float* __restrict__ oas1, float* __restrict__ oad1,
    float* __restrict__ oas2, float* __restrict__ oad2)
{
    const int b = blockIdx.x, tid = threadIdx.x;
    if (b < FILL_BLOCKS) {
        int j0 = b * 512 + tid;
#pragma unroll
        for (int q = 0; q < 2; q++) {
            int j = j0 + q * 256;
            const int* ei; int* cu; int* cs; int e;
            if (j < EE) { ei = eic; cu = cur;      cs = csr;      e = j; }
            else        { ei = eil; cu = cur + NN; cs = csr + EE; e = j - EE; }
            int s = ei[e], d = ei[EE + e];
            int pos = atomicAdd(&cu[d], 1);
            cs[pos] = s;
        }
    } else {
        int node = ((b - FILL_BLOCKS) * 256 + tid) >> 5;
        if (node >= NN) return;
        int lane = tid & 31;
        int hl = lane >> 4;
#pragma unroll
        for (int L = 0; L < 2; L++) {
            const __half* h = (L == 0) ? h1 : h2;
            const float* ats = (L == 0) ? as1 : as2;
            const float* atd = (L == 0) ? ad1 : ad2;
            float* oas = (L == 0) ? oas1 : oas2;
            float* oad = (L == 0) ? oad1 : oad2;

            uint2 raw = *(const uint2*)&h[(size_t)node * 128 + lane * 4];
            float2 f0 = __half22float2(*(__half2*)&raw.x);
            float2 f1 = __half22float2(*(__half2*)&raw.y);
            float4 sv = *(const float4*)&ats[lane * 4];
            float4 dv = *(const float4*)&atd[lane * 4];
            float ps = f0.x * sv.x + f0.y * sv.y + f1.x * sv.z + f1.y * sv.w;
            float pd = f0.x * dv.x + f0.y * dv.y + f1.x * dv.z + f1.y * dv.w;
#pragma unroll
            for (int o = 8; o > 0; o >>= 1) {
                ps += __shfl_xor_sync(0xffffffffu, ps, o);
                pd += __shfl_xor_sync(0xffffffffu, pd, o);
            }
            if ((lane & 15) == 0) {
                oas[node * 2 + hl] = ps;
                oad[node * 2 + hl] = pd;
            }
        }
    }
}

// ================= aggregation: both layers, one warp per dst, 2-edge unroll =====
__global__ __launch_bounds__(256) void agg2_kernel(
    const __half* __restrict__ h1, const __half* __restrict__ h2,
    const float* __restrict__ pas1, const float* __restrict__ pad1,
    const float* __restrict__ pas2, const float* __restrict__ pad2,
    const int* __restrict__ offsA, const int* __restrict__ csrA,
    const float* __restrict__ b1, const float* __restrict__ b2,
    float* __restrict__ xcomb)
{
    int g = blockIdx.x * 8 + (threadIdx.x >> 5);
    int layer = (g >= NN);
    int node = g - layer * NN;
    int lane = threadIdx.x & 31;
    int hl = lane >> 4;
    int c4 = (lane & 15) * 4;

    const __half* h   = layer ? h2 : h1;
    const float* asrc = layer ? pas2 : pas1;
    const float* adst = layer ? pad2 : pad1;
    const int* offs   = offsA + layer * (NN + 1);
    const int* csr    = csrA + layer * EE;
    const float* bias = layer ? b2 : b1;
    const int colOff  = layer * 128;

    float ad = adst[node * 2 + hl];

    // self loop (analytic)
    float e = asrc[node * 2 + hl] + ad;
    e = (e > 0.f) ? e : 0.2f * e;
    float p = __expf(e);
    float sum = p;
    uint2 raw = *(const uint2*)&h[(size_t)node * 128 + hl * 64 + c4];
    float2 f0 = __half22float2(*(__half2*)&raw.x);
    float2 f1 = __half22float2(*(__half2*)&raw.y);
    float4 acc = make_float4(f0.x * p, f0.y * p, f1.x * p, f1.y * p);

    int beg = offs[node], end = offs[node + 1];
    int j = beg;
    int n2 = beg + ((end - beg) & ~1);
    for (; j < n2; j += 2) {
        int s0 = csr[j], s1 = csr[j + 1];
        float a0 = asrc[s0 * 2 + hl];
        float a1 = asrc[s1 * 2 + hl];
        uint2 r0 = *(const uint2*)&h[(size_t)s0 * 128 + hl * 64 + c4];
        uint2 r1 = *(const uint2*)&h[(size_t)s1 * 128 + hl * 64 + c4];
        float e0 = a0 + ad; e0 = (e0 > 0.f) ? e0 : 0.2f * e0;
        float e1 = a1 + ad; e1 = (e1 > 0.f) ? e1 : 0.2f * e1;
        float p0 = __expf(e0), p1 = __expf(e1);
        sum += p0 + p1;
        float2 g0 = __half22float2(*(__half2*)&r0.x);
        float2 g1 = __half22float2(*(__half2*)&r0.y);
        float2 g2 = __half22float2(*(__half2*)&r1.x);
        float2 g3 = __half22float2(*(__half2*)&r1.y);
        acc.x = fmaf(g0.x, p0, fmaf(g2.x, p1, acc.x));
        acc.y = fmaf(g0.y, p0, fmaf(g2.y, p1, acc.y));
        acc.z = fmaf(g1.x, p0, fmaf(g3.x, p1, acc.z));
        acc.w = fmaf(g1.y, p0, fmaf(g3.y, p1, acc.w));
    }
    if (j < end) {
        int s = csr[j];
        float e2 = asrc[s * 2 + hl] + ad;
        e2 = (e2 > 0.f) ? e2 : 0.2f * e2;
        float p2 = __expf(e2);
        sum += p2;
        uint2 r2 = *(const uint2*)&h[(size_t)s * 128 + hl * 64 + c4];
        float2 g0 = __half22float2(*(__half2*)&r2.x);
        float2 g1 = __half22float2(*(__half2*)&r2.y);
        acc.x = fmaf(g0.x, p2, acc.x);
        acc.y = fmaf(g0.y, p2, acc.y);
        acc.z = fmaf(g1.x, p2, acc.z);
        acc.w = fmaf(g1.y, p2, acc.w);
    }

    float inv = 1.f / sum;
    float4 bv = *(const float4*)&bias[hl * 64 + c4];
    float4 r;
    r.x = fmaxf(fmaf(acc.x, inv, bv.x), 0.f);
    r.y = fmaxf(fmaf(acc.y, inv, bv.y), 0.f);
    r.z = fmaxf(fmaf(acc.z, inv, bv.z), 0.f);
    r.w = fmaxf(fmaf(acc.w, inv, bv.w), 0.f);
    *(float4*)&xcomb[(size_t)node * 256 + colOff + hl * 64 + c4] = r;
}

// ================= FC GEMM (inline hi/lo split, NF=64) =================
__global__ __launch_bounds__(256) void gemm_fc_kernel(
    const float* __restrict__ A, const __nv_bfloat16* __restrict__ Wt,
    const float* __restrict__ bias, float* __restrict__ C, int M, int numTiles)
{
    constexpr int NF = 64, NT = 4;
    constexpr int WIMG = NF * 512;       // 32768
    constexpr int OFF_A = 2 * WIMG;      // 65536

    extern __shared__ __align__(16) char smem[];
    const uint32_t sb = smem_to_u32(smem);
    const int tid = threadIdx.x, wid = tid >> 5, lane = tid & 31;
    const int wm = wid & 3, wn = wid >> 2;
    const int wnb = wn * 32;

    for (int i = tid; i < NF * 64; i += 256)
        cp_async16(sb + (uint32_t)i * 16u, ((const uint4*)Wt) + i);
    CP_COMMIT();
    CP_WAIT(0);
    __syncthreads();

    const int r15 = lane & 15, rh = lane >> 4;
    float4 pa[8];

    for (int tile = blockIdx.x; tile < numTiles; tile += gridDim.x) {
        const int m0 = tile * 128;
        float acc[2][NT][4];
#pragma unroll
        for (int mt = 0; mt < 2; mt++)
#pragma unroll
            for (int nt = 0; nt < NT; nt++)
#pragma unroll
                for (int q = 0; q < 4; q++) acc[mt][nt][q] = 0.f;

#pragma unroll
        for (int i = 0; i < 8; i++) {
            int p = i * 256 + tid, row = p >> 4, c4 = p & 15, gm = m0 + row;
            pa[i] = (gm < M) ? *(const float4*)&A[(size_t)gm * 256 + c4 * 4]
                             : make_float4(0.f, 0.f, 0.f, 0.f);
        }

#pragma unroll
        for (int kc = 0; kc < 4; kc++) {
            const int buf = kc & 1;
            const uint32_t aOff = OFF_A + (uint32_t)buf * 32768u;
#pragma unroll
            for (int i = 0; i < 8; i++) {
                int p = i * 256 + tid, row = p >> 4, c4 = p & 15;
                float4 v = pa[i];
                __nv_bfloat16 h0 = __float2bfloat16_rn(v.x);
                __nv_bfloat16 h1 = __float2bfloat16_rn(v.y);
                __nv_bfloat16 h2 = __float2bfloat16_rn(v.z);
                __nv_bfloat16 h3 = __float2bfloat16_rn(v.w);
                int u = c4 >> 1, hw = (c4 & 1) * 8;
                uint32_t base = (uint32_t)row * 128u +
                                (uint32_t)((u ^ (row & 7)) << 4) + (uint32_t)hw;
                __nv_bfloat162 hp0 = __halves2bfloat162(h0, h1);
                __nv_bfloat162 hp1 = __halves2bfloat162(h2, h3);
                *(uint2*)(smem + aOff + base) =
                    make_uint2(bf2bits(hp0), bf2bits(hp1));
                *(uint2*)(smem + aOff + 16384u + base) = make_uint2(
                    bfpack(v.x - __bfloat162float(h0), v.y - __bfloat162float(h1)),
                    bfpack(v.z - __bfloat162float(h2), v.w - __bfloat162float(h3)));
            }
            __syncthreads();

            if (kc < 3) {
#pragma unroll
                for (int i = 0; i < 8; i++) {
                    int p = i * 256 + tid, row = p >> 4, c4 = p & 15, gm = m0 + row;
                    pa[i] = (gm < M)
                        ? *(const float4*)&A[(size_t)gm * 256 + (kc + 1) * 64 + c4 * 4]
                        : make_float4(0.f, 0.f, 0.f, 0.f);
                }
            }

            const uint32_t aH = sb + aOff;
            const uint32_t aL = aH + 16384u;
            const uint32_t bH = sb + (uint32_t)kc * (NF * 128u);
            const uint32_t bL = bH + (uint32_t)WIMG;
#pragma unroll
            for (int k16 = 0; k16 < 4; k16++) {
                uint32_t ah[2][4], al[2][4];
#pragma unroll
                for (int mt = 0; mt < 2; mt++) {
                    int row = wm * 32 + mt * 16 + r15;
                    uint32_t off = (uint32_t)row * 128u +
                                   (uint32_t)(((k16 * 2 + rh) ^ (row & 7)) << 4);
                    ldmatrix_x4(ah[mt], aH + off);
                    ldmatrix_x4(al[mt], aL + off);
                }
#pragma unroll
                for (int nt = 0; nt < NT; nt++) {
                    int rn = wnb + nt * 8 + (lane & 7);
                    int un = k16 * 2 + ((lane >> 3) & 1);
                    uint32_t off = (uint32_t)rn * 128u +
                                   (uint32_t)((un ^ (rn & 7)) << 4);
                    uint32_t bh[2], bl[2];
                    ldmatrix_x2(bh, bH + off);
                    ldmatrix_x2(bl, bL + off);
#pragma unroll
                    for (int mt = 0; mt < 2; mt++) {
                        mma16816(acc[mt][nt], ah[mt], bh);
                        mma16816(acc[mt][nt], ah[mt], bl);
                        mma16816(acc[mt][nt], al[mt], bh);
                    }
                }
            }
            __syncthreads();
        }

#pragma unroll
        for (int nt = 0; nt < NT; nt++) {
            int col = wnb + nt * 8 + (lane & 3) * 2;
            float bx = bias[col], by = bias[col + 1];
#pragma unroll
            for (int mt = 0; mt < 2; mt++) {
                int row = m0 + wm * 32 + mt * 16 + (lane >> 2);
                if (row < M) {
                    float2 o = make_float2(acc[mt][nt][0] + bx, acc[mt][nt][1] + by);
                    *(float2*)&C[(size_t)row * NF + col] = o;
                }
                if (row + 8 < M) {
                    float2 o = make_float2(acc[mt][nt][2] + bx, acc[mt][nt][3] + by);
                    *(float2*)&C[(size_t)(row + 8) * NF + col] = o;
                }
            }
        }
    }
}

// ---------------- launch ----------------
extern "C" void kernel_launch(void* const* d_in, const int* in_sizes, int n_in,
                              void* d_out, int out_size) {
    const float* x    = (const float*)d_in[0];
    const int*   eic  = (const int*)d_in[1];
    const int*   eil  = (const int*)d_in[2];
    const float* W1   = (const float*)d_in[3];
    const float* as1  = (const float*)d_in[4];
    const float* ad1  = (const float*)d_in[5];
    const float* b1   = (const float*)d_in[6];
    const float* W2   = (const float*)d_in[7];
    const float* as2  = (const float*)d_in[8];
    const float* ad2  = (const float*)d_in[9];
    const float* b2   = (const float*)d_in[10];
    const float* fcW  = (const float*)d_in[11];
    const float* fcb  = (const float*)d_in[12];
    float* out = (float*)d_out;

    __half *h1, *h2;
    float *xcomb, *pas1, *pad1, *pas2, *pad2;
    int *cnt, *offs, *cur, *csr;
    __nv_bfloat16 *w1, *w2, *wf;
    cudaGetSymbolAddress((void**)&h1, g_h1);
    cudaGetSymbolAddress((void**)&h2, g_h2);
    cudaGetSymbolAddress((void**)&xcomb, g_xcomb);
    cudaGetSymbolAddress((void**)&pas1, g_as1);
    cudaGetSymbolAddress((void**)&pad1, g_ad1);
    cudaGetSymbolAddress((void**)&pas2, g_as2);
    cudaGetSymbolAddress((void**)&pad2, g_ad2);
    cudaGetSymbolAddress((void**)&cnt, g_cnt);
    cudaGetSymbolAddress((void**)&offs, g_offs);
    cudaGetSymbolAddress((void**)&cur, g_cur);
    cudaGetSymbolAddress((void**)&csr, g_csr);
    cudaGetSymbolAddress((void**)&w1, g_w1);
    cudaGetSymbolAddress((void**)&w2, g_w2);
    cudaGetSymbolAddress((void**)&wf, g_wf);

    constexpr int SMEM_H = 131072 + 65536;   // 196608
    constexpr int SMEM_F = 65536 + 65536;    // 131072
    cudaFuncSetAttribute(gemm_h_kernel,
                         cudaFuncAttributeMaxDynamicSharedMemorySize, SMEM_H);
    cudaFuncSetAttribute(gemm_fc_kernel,
                         cudaFuncAttributeMaxDynamicSharedMemorySize, SMEM_F);

    // 1. zero counters
    cudaMemsetAsync(cnt, 0, 2 * NN * sizeof(int));

    // 2. phase1: count edges + prep weights
    phase1_kernel<<<CNT_BLOCKS + PW_BLOCKS, 256>>>(
        eic, eil, W1, W2, fcW, w1, w2, wf, cnt);

    // 3. scan
    scan2_kernel<<<2, 1024>>>(cnt, offs, cur);

    // 4. both h-GEMMs in one launch (inline conversion)
    gemm_h_kernel<<<148, 256, SMEM_H>>>(x, w1, w2, h1, h2);

    // 5. fill CSR + attention coefficients
    phase3_kernel<<<FILL_BLOCKS + CNT_BLOCKS, 256>>>(eic, eil, cur, csr, h1, h2,
                                                     as1, ad1, as2, ad2,
                                                     pas1, pad1, pas2, pad2);

    // 6. aggregation (both layers, 2-edge unrolled)
    agg2_kernel<<<25000, 256>>>(h1, h2, pas1, pad1, pas2, pad2,
                                offs, csr, b1, b2, xcomb);

    // 7. final FC
    gemm_fc_kernel<<<148, 256, SMEM_F>>>(xcomb, wf, fcb, out, NN, NTILES);
}

// round 16
// speedup vs baseline: 1.0382x; 1.0382x over previous
#include <cuda_runtime.h>
#include <cuda_bf16.h>
#include <cuda_fp16.h>
#include <cstdint>

#define NN 100000
#define EE 1600000
#define NTILES 782          // ceil(NN/128)

// ---------------- scratch (no allocation allowed) ----------------
__device__ __half g_h1[NN * 128];
__device__ __half g_h2[NN * 128];
__device__ __half g_xcomb[NN * 256];
__device__ float  g_as1[NN * 2];
__device__ float  g_ad1[NN * 2];
__device__ float  g_as2[NN * 2];
__device__ float  g_ad2[NN * 2];
__device__ int    g_cnt[2 * NN];
__device__ int    g_offs[2 * (NN + 1)];
__device__ int    g_cur[2 * NN];
__device__ int    g_csr[2 * EE];
// pre-split, pre-swizzled x images: per tile, per 64-k chunk: hi 16KB + lo 16KB
__device__ uint4  g_xs[NTILES * 8192];
// W^T bf16 hi image + lo image (swizzled, chunk-major)
__device__ __align__(16) __nv_bfloat16 g_w1[128 * 512];
__device__ __align__(16) __nv_bfloat16 g_w2[128 * 512];
__device__ __align__(16) __nv_bfloat16 g_wf[64 * 512];

// ---------------- helpers ----------------
__device__ __forceinline__ uint32_t smem_to_u32(const void* p) {
    uint32_t a;
    asm("{ .reg .u64 t; cvta.to.shared.u64 t, %1; cvt.u32.u64 %0, t; }" : "=r"(a) : "l"(p));
    return a;
}
__device__ __forceinline__ void ldmatrix_x4(uint32_t* r, uint32_t addr) {
    asm volatile("ldmatrix.sync.aligned.m8n8.x4.shared.b16 {%0,%1,%2,%3}, [%4];"
        : "=r"(r[0]), "=r"(r[1]), "=r"(r[2]), "=r"(r[3]) : "r"(addr));
}
__device__ __forceinline__ void ldmatrix_x2(uint32_t* r, uint32_t addr) {
    asm volatile("ldmatrix.sync.aligned.m8n8.x2.shared.b16 {%0,%1}, [%2];"
        : "=r"(r[0]), "=r"(r[1]) : "r"(addr));
}
__device__ __forceinline__ void mma16816(float* c, const uint32_t* a, const uint32_t* b) {
    asm volatile(
        "mma.sync.aligned.m16n8k16.row.col.f32.bf16.bf16.f32 "
        "{%0,%1,%2,%3},{%4,%5,%6,%7},{%8,%9},{%0,%1,%2,%3};"
        : "+f"(c[0]), "+f"(c[1]), "+f"(c[2]), "+f"(c[3])
        : "r"(a[0]), "r"(a[1]), "r"(a[2]), "r"(a[3]), "r"(b[0]), "r"(b[1]));
}
__device__ __forceinline__ void cp_async16(uint32_t dst, const void* src) {
    asm volatile("cp.async.cg.shared.global [%0], [%1], 16;" :: "r"(dst), "l"(src));
}
#define CP_COMMIT() asm volatile("cp.async.commit_group;")
#define CP_WAIT(n)  asm volatile("cp.async.wait_group %0;" :: "n"(n))
__device__ __forceinline__ uint32_t bf2bits(__nv_bfloat162 v) {
    return *reinterpret_cast<uint32_t*>(&v);
}
__device__ __forceinline__ uint32_t bfpack(float a, float b) {
    __nv_bfloat162 t = __halves2bfloat162(__float2bfloat16_rn(a), __float2bfloat16_rn(b));
    return *reinterpret_cast<uint32_t*>(&t);
}
__device__ __forceinline__ uint32_t h2bits(__half2 v) {
    return *reinterpret_cast<uint32_t*>(&v);
}

// ================= phase1: prep_x + count + prep_w (fused) =================
#define PX_BLOCKS 12512     // 782*4*128*8 / 256
#define CNT_BLOCKS 12500    // 2*EE / 256
#define PW_BLOCKS 320       // 81920 / 256
#define FILL_BLOCKS 6250    // 2*EE / 512

__global__ __launch_bounds__(256) void phase1_kernel(
    const float* __restrict__ x,
    const int* __restrict__ eic, const int* __restrict__ eil,
    const float* __restrict__ W1, const float* __restrict__ W2,
    const float* __restrict__ Wf,
    uint4* __restrict__ xs,
    __nv_bfloat16* __restrict__ o1, __nv_bfloat16* __restrict__ o2,
    __nv_bfloat16* __restrict__ of,
    int* __restrict__ cnt)
{
    const int b = blockIdx.x, tid = threadIdx.x;
    if (b < PX_BLOCKS) {
        // ---- pre-split x into swizzled bf16 hi/lo tile images ----
        int id = b * 256 + tid;
        int u = id & 7, r = (id >> 3) & 127, kc = (id >> 10) & 3, tile = id >> 12;
        int gm = tile * 128 + r;
        float4 v0 = make_float4(0.f, 0.f, 0.f, 0.f), v1 = v0;
        if (gm < NN) {
            const float* src = &x[(size_t)gm * 256 + kc * 64 + u * 8];
            v0 = *(const float4*)src;
            v1 = *(const float4*)(src + 4);
        }
        float f[8] = {v0.x, v0.y, v0.z, v0.w, v1.x, v1.y, v1.z, v1.w};
        uint32_t hi[4], lo[4];
#pragma unroll
        for (int q = 0; q < 4; q++) {
            __nv_bfloat16 ha = __float2bfloat16_rn(f[2 * q]);
            __nv_bfloat16 hb = __float2bfloat16_rn(f[2 * q + 1]);
            __nv_bfloat162 hp = __halves2bfloat162(ha, hb);
            hi[q] = *reinterpret_cast<uint32_t*>(&hp);
            lo[q] = bfpack(f[2 * q] - __bfloat162float(ha),
                           f[2 * q + 1] - __bfloat162float(hb));
        }
        int unit = r * 8 + (u ^ (r & 7));
        uint4* base = xs + (size_t)tile * 8192 + kc * 2048;
        base[unit]        = make_uint4(hi[0], hi[1], hi[2], hi[3]);
        base[1024 + unit] = make_uint4(lo[0], lo[1], lo[2], lo[3]);
    } else if (b < PX_BLOCKS + CNT_BLOCKS) {
        // ---- count incoming edges (both layers) ----
        int j = (b - PX_BLOCKS) * 256 + tid;
        if (j < EE)          atomicAdd(&cnt[eic[EE + j]], 1);
        else                 atomicAdd(&cnt[NN + eil[EE + (j - EE)]], 1);
    } else {
        // ---- prep weights: hi/lo swizzled images ----
        int id = (b - PX_BLOCKS - CNT_BLOCKS) * 256 + tid;
        const float* W; __nv_bfloat16* o; int NF, li;
        if (id < 32768)      { W = W1; o = o1; NF = 128; li = id; }
        else if (id < 65536) { W = W2; o = o2; NF = 128; li = id - 32768; }
        else                 { W = Wf; o = of; NF = 64;  li = id - 65536; }
        int n = li % NF, k = li / NF;
        float v = W[li];
        __nv_bfloat16 hv = __float2bfloat16_rn(v);
        __nv_bfloat16 lv = __float2bfloat16_rn(v - __bfloat162float(hv));
        uint32_t off = (uint32_t)((k >> 6) * NF + n) * 128u
                     + (uint32_t)((((k & 63) >> 3) ^ (n & 7)) << 4)
                     + (uint32_t)(k & 7) * 2u;
        *(__nv_bfloat16*)((char*)o + off) = hv;
        *(__nv_bfloat16*)((char*)(o + NF * 256) + off) = lv;
    }
}

// ================= scan (exclusive prefix per layer) =================
__global__ __launch_bounds__(1024) void scan2_kernel(
    const int* __restrict__ cntA, int* __restrict__ offsA, int* __restrict__ curA)
{
    const int L = blockIdx.x;
    const int* cnt = cntA + L * NN;
    int* offs = offsA + L * (NN + 1);
    int* cur  = curA + L * NN;

    __shared__ int sums[1024];
    const int CH = (NN + 1023) / 1024;
    int t = threadIdx.x;
    int base = t * CH;
    int local = 0;
    for (int i = 0; i < CH; i++) {
        int idx = base + i;
        if (idx < NN) local += cnt[idx];
    }
    sums[t] = local;
    __syncthreads();
#pragma unroll
    for (int off = 1; off < 1024; off <<= 1) {
        int v = (t >= off) ? sums[t - off] : 0;
        __syncthreads();
        sums[t] += v;
        __syncthreads();
    }
    int run = sums[t] - local;
    for (int i = 0; i < CH; i++) {
        int idx = base + i;
        if (idx < NN) {
            offs[idx] = run;
            cur[idx] = run;
            run += cnt[idx];
        }
    }
    if (base < NN && base + CH >= NN) offs[NN] = run;
}

// ================= h-GEMM: both layers, pre-split A via cp.async =================
// 148 CTAs: even -> layer1, odd -> layer2 (74 each, strided tiles).
// C = Ahi*Whi + Ahi*Wlo + Alo*Whi, fp32 acc, fp16 output.
__global__ __launch_bounds__(256) void gemm_h_kernel(
    const uint4* __restrict__ xs,
    const __nv_bfloat16* __restrict__ w1, const __nv_bfloat16* __restrict__ w2,
    __half* __restrict__ h1, __half* __restrict__ h2)
{
    constexpr int NT = 8;
    constexpr int OFF_A = 131072;         // after 2 W images (64KB each)

    extern __shared__ __align__(16) char smem[];
    const uint32_t sb = smem_to_u32(smem);
    const int tid = threadIdx.x, wid = tid >> 5, lane = tid & 31;
    const int wm = wid & 3, wn = wid >> 2;
    const int wnb = wn * 64;

    const int half_ = blockIdx.x & 1;
    const int cidx = blockIdx.x >> 1;     // 0..73
    const __nv_bfloat16* Wt = half_ ? w2 : w1;
    __half* H = half_ ? h2 : h1;

    // W images -> smem once
    for (int i = tid; i < 8192; i += 256)
        cp_async16(sb + (uint32_t)i * 16u, ((const uint4*)Wt) + i);
    CP_COMMIT();
    CP_WAIT(0);
    __syncthreads();

    const int r15 = lane & 15, rh = lane >> 4;

    auto issueA = [&](int tile, int kc, int buf) {
        uint32_t dst = sb + OFF_A + (uint32_t)buf * 32768u;
        const uint4* src = xs + (size_t)tile * 8192 + kc * 2048;
#pragma unroll
        for (int i = 0; i < 8; i++)
            cp_async16(dst + (uint32_t)(i * 256 + tid) * 16u, src + i * 256 + tid);
        CP_COMMIT();
    };

    auto mmaChunk = [&](int kc, int buf, float acc[2][NT][4]) {
        const uint32_t aH = sb + OFF_A + (uint32_t)buf * 32768u;
        const uint32_t aL = aH + 16384u;
        const uint32_t bH = sb + (uint32_t)kc * 16384u;
        const uint32_t bL = bH + 65536u;
#pragma unroll
        for (int k16 = 0; k16 < 4; k16++) {
            uint32_t ah[2][4], al[2][4];
#pragma unroll
            for (int mt = 0; mt < 2; mt++) {
                int row = wm * 32 + mt * 16 + r15;
                uint32_t off = (uint32_t)row * 128u +
                               (uint32_t)(((k16 * 2 + rh) ^ (row & 7)) << 4);
                ldmatrix_x4(ah[mt], aH + off);
                ldmatrix_x4(al[mt], aL + off);
            }
#pragma unroll
            for (int nt = 0; nt < NT; nt++) {
                int rn = wnb + nt * 8 + (lane & 7);
                int un = k16 * 2 + ((lane >> 3) & 1);
                uint32_t off = (uint32_t)rn * 128u + (uint32_t)((un ^ (rn & 7)) << 4);
                uint32_t bh[2], bl[2];
                ldmatrix_x2(bh, bH + off);
                ldmatrix_x2(bl, bL + off);
#pragma unroll
                for (int mt = 0; mt < 2; mt++) {
                    mma16816(acc[mt][nt], ah[mt], bh);
                    mma16816(acc[mt][nt], ah[mt], bl);
                    mma16816(acc[mt][nt], al[mt], bh);
                }
            }
        }
    };

    int tile = cidx;
    if (tile < NTILES) { issueA(tile, 0, 0); issueA(tile, 1, 1); }

    for (; tile < NTILES; tile += 74) {
        const int m0 = tile * 128;
        const int nxt = tile + 74;
        const bool hasNext = (nxt < NTILES);
        float acc[2][NT][4];
#pragma unroll
        for (int mt = 0; mt < 2; mt++)
#pragma unroll
            for (int nt = 0; nt < NT; nt++)
#pragma unroll
                for (int q = 0; q < 4; q++) acc[mt][nt][q] = 0.f;

        // kc = 0
        CP_WAIT(1); __syncthreads();
        mmaChunk(0, 0, acc); __syncthreads();
        issueA(tile, 2, 0);
        // kc = 1
        CP_WAIT(1); __syncthreads();
        mmaChunk(1, 1, acc); __syncthreads();
        issueA(tile, 3, 1);
        // kc = 2
        CP_WAIT(1); __syncthreads();
        mmaChunk(2, 0, acc); __syncthreads();
        if (hasNext) issueA(nxt, 0, 0);
        // kc = 3
        if (hasNext) { CP_WAIT(1); } else { CP_WAIT(0); }
        __syncthreads();
        mmaChunk(3, 1, acc); __syncthreads();
        if (hasNext) issueA(nxt, 1, 1);

        // epilogue: fp32 acc -> fp16 stores
#pragma unroll
        for (int nt = 0; nt < NT; nt++) {
            int col = wnb + nt * 8 + (lane & 3) * 2;
#pragma unroll
            for (int mt = 0; mt < 2; mt++) {
                int row = m0 + wm * 32 + mt * 16 + (lane >> 2);
                if (row < NN) {
                    __half2 v = __floats2half2_rn(acc[mt][nt][0], acc[mt][nt][1]);
                    *(__half2*)&H[(size_t)row * 128 + col] = v;
                }
                if (row + 8 < NN) {
                    __half2 v = __floats2half2_rn(acc[mt][nt][2], acc[mt][nt][3]);
                    *(__half2*)&H[(size_t)(row + 8) * 128 + col] = v;
                }
            }
        }
    }
}

// ================= phase3: fill CSR (2 edges/thread) + acoef (fused) =================
__global__ __launch_bounds__(256) void phase3_kernel(
    const int* __restrict__ eic, const int* __restrict__ eil,
    int* __restrict__ cur, int* __restrict__ csr,
    const __half* __restrict__ h1, const __half* __restrict__ h2,
    const float* __restrict__ as1, const float* __restrict__ ad1,
    const float* __restrict__ as2, const float* __restrict__ ad2,
    float* __restrict__ oas1, float* __restrict__ oad1,
    float* __restrict__ oas2, float* __restrict__ oad2)
{
    const int b = blockIdx.x, tid = threadIdx.x;
    if (b < FILL_BLOCKS) {
        int j0 = b * 512 + tid;
#pragma unroll
        for (int q = 0; q < 2; q++) {
            int j = j0 + q * 256;
            const int* ei; int* cu; int* cs; int e;
            if (j < EE) { ei = eic; cu = cur;      cs = csr;      e = j; }
            else        { ei = eil; cu = cur + NN; cs = csr + EE; e = j - EE; }
            int s = ei[e], d = ei[EE + e];
            int pos = atomicAdd(&cu[d], 1);
            cs[pos] = s;
        }
    } else {
        int node = ((b - FILL_BLOCKS) * 256 + tid) >> 5;
        if (node >= NN) return;
        int lane = tid & 31;
        int hl = lane >> 4;
#pragma unroll
        for (int L = 0; L < 2; L++) {
            const __half* h = (L == 0) ? h1 : h2;
            const float* ats = (L == 0) ? as1 : as2;
            const float* atd = (L == 0) ? ad1 : ad2;
            float* oas = (L == 0) ? oas1 : oas2;
            float* oad = (L == 0) ? oad1 : oad2;

            uint2 raw = *(const uint2*)&h[(size_t)node * 128 + lane * 4];
            float2 f0 = __half22float2(*(__half2*)&raw.x);
            float2 f1 = __half22float2(*(__half2*)&raw.y);
            float4 sv = *(const float4*)&ats[lane * 4];
            float4 dv = *(const float4*)&atd[lane * 4];
            float ps = f0.x * sv.x + f0.y * sv.y + f1.x * sv.z + f1.y * sv.w;
            float pd = f0.x * dv.x + f0.y * dv.y + f1.x * dv.z + f1.y * dv.w;
#pragma unroll
            for (int o = 8; o > 0; o >>= 1) {
                ps += __shfl_xor_sync(0xffffffffu, ps, o);
                pd += __shfl_xor_sync(0xffffffffu, pd, o);
            }
            if ((lane & 15) == 0) {
                oas[node * 2 + hl] = ps;
                oad[node * 2 + hl] = pd;
            }
        }
    }
}

// ================= aggregation: both layers, one warp per dst, 2-edge unroll =====
// output fp16 xcomb
__global__ __launch_bounds__(256) void agg2_kernel(
    const __half* __restrict__ h1, const __half* __restrict__ h2,
    const float* __restrict__ pas1, const float* __restrict__ pad1,
    const float* __restrict__ pas2, const float* __restrict__ pad2,
    const int* __restrict__ offsA, const int* __restrict__ csrA,
    const float* __restrict__ b1, const float* __restrict__ b2,
    __half* __restrict__ xcomb)
{
    int g = blockIdx.x * 8 + (threadIdx.x >> 5);
    int layer = (g >= NN);
    int node = g - layer * NN;
    int lane = threadIdx.x & 31;
    int hl = lane >> 4;
    int c4 = (lane & 15) * 4;

    const __half* h   = layer ? h2 : h1;
    const float* asrc = layer ? pas2 : pas1;
    const float* adst = layer ? pad2 : pad1;
    const int* offs   = offsA + layer * (NN + 1);
    const int* csr    = csrA + layer * EE;
    const float* bias = layer ? b2 : b1;
    const int colOff  = layer * 128;

    float ad = adst[node * 2 + hl];

    // self loop (analytic)
    float e = asrc[node * 2 + hl] + ad;
    e = (e > 0.f) ? e : 0.2f * e;
    float p = __expf(e);
    float sum = p;
    uint2 raw = *(const uint2*)&h[(size_t)node * 128 + hl * 64 + c4];
    float2 f0 = __half22float2(*(__half2*)&raw.x);
    float2 f1 = __half22float2(*(__half2*)&raw.y);
    float4 acc = make_float4(f0.x * p, f0.y * p, f1.x * p, f1.y * p);

    int beg = offs[node], end = offs[node + 1];
    int j = beg;
    int n2 = beg + ((end - beg) & ~1);
    for (; j < n2; j += 2) {
        int s0 = csr[j], s1 = csr[j + 1];
        float a0 = asrc[s0 * 2 + hl];
        float a1 = asrc[s1 * 2 + hl];
        uint2 r0 = *(const uint2*)&h[(size_t)s0 * 128 + hl * 64 + c4];
        uint2 r1 = *(const uint2*)&h[(size_t)s1 * 128 + hl * 64 + c4];
        float e0 = a0 + ad; e0 = (e0 > 0.f) ? e0 : 0.2f * e0;
        float e1 = a1 + ad; e1 = (e1 > 0.f) ? e1 : 0.2f * e1;
        float p0 = __expf(e0), p1 = __expf(e1);
        sum += p0 + p1;
        float2 g0 = __half22float2(*(__half2*)&r0.x);
        float2 g1 = __half22float2(*(__half2*)&r0.y);
        float2 g2 = __half22float2(*(__half2*)&r1.x);
        float2 g3 = __half22float2(*(__half2*)&r1.y);
        acc.x = fmaf(g0.x, p0, fmaf(g2.x, p1, acc.x));
        acc.y = fmaf(g0.y, p0, fmaf(g2.y, p1, acc.y));
        acc.z = fmaf(g1.x, p0, fmaf(g3.x, p1, acc.z));
        acc.w = fmaf(g1.y, p0, fmaf(g3.y, p1, acc.w));
    }
    if (j < end) {
        int s = csr[j];
        float e2 = asrc[s * 2 + hl] + ad;
        e2 = (e2 > 0.f) ? e2 : 0.2f * e2;
        float p2 = __expf(e2);
        sum += p2;
        uint2 r2 = *(const uint2*)&h[(size_t)s * 128 + hl * 64 + c4];
        float2 g0 = __half22float2(*(__half2*)&r2.x);
        float2 g1 = __half22float2(*(__half2*)&r2.y);
        acc.x = fmaf(g0.x, p2, acc.x);
        acc.y = fmaf(g0.y, p2, acc.y);
        acc.z = fmaf(g1.x, p2, acc.z);
        acc.w = fmaf(g1.y, p2, acc.w);
    }

    float inv = 1.f / sum;
    float4 bv = *(const float4*)&bias[hl * 64 + c4];
    float rx = fmaxf(fmaf(acc.x, inv, bv.x), 0.f);
    float ry = fmaxf(fmaf(acc.y, inv, bv.y), 0.f);
    float rz = fmaxf(fmaf(acc.z, inv, bv.z), 0.f);
    float rw = fmaxf(fmaf(acc.w, inv, bv.w), 0.f);
    uint2 st;
    st.x = h2bits(__floats2half2_rn(rx, ry));
    st.y = h2bits(__floats2half2_rn(rz, rw));
    *(uint2*)&xcomb[(size_t)node * 256 + colOff + hl * 64 + c4] = st;
}

// ================= FC GEMM (fp16 A, inline bf16 hi/lo split, NF=64) =================
__global__ __launch_bounds__(256) void gemm_fc_kernel(
    const __half* __restrict__ A, const __nv_bfloat16* __restrict__ Wt,
    const float* __restrict__ bias, float* __restrict__ C, int M, int numTiles)
{
    constexpr int NF = 64, NT = 4;
    constexpr int WIMG = NF * 512;       // 32768
    constexpr int OFF_A = 2 * WIMG;      // 65536

    extern __shared__ __align__(16) char smem[];
    const uint32_t sb = smem_to_u32(smem);
    const int tid = threadIdx.x, wid = tid >> 5, lane = tid & 31;
    const int wm = wid & 3, wn = wid >> 2;
    const int wnb = wn * 32;

    for (int i = tid; i < NF * 64; i += 256)
        cp_async16(sb + (uint32_t)i * 16u, ((const uint4*)Wt) + i);
    CP_COMMIT();
    CP_WAIT(0);
    __syncthreads();

    const int r15 = lane & 15, rh = lane >> 4;
    uint4 pa[4];   // 4 x 8 fp16 per thread per chunk (128 rows x 64 cols fp16 = 1024 uint4)

    for (int tile = blockIdx.x; tile < numTiles; tile += gridDim.x) {
        const int m0 = tile * 128;
        float acc[2][NT][4];
#pragma unroll
        for (int mt = 0; mt < 2; mt++)
#pragma unroll
            for (int nt = 0; nt < NT; nt++)
#pragma unroll
                for (int q = 0; q < 4; q++) acc[mt][nt][q] = 0.f;

        // prefetch chunk 0
#pragma unroll
        for (int i = 0; i < 4; i++) {
            int p = i * 256 + tid, row = p >> 3, u8 = p & 7, gm = m0 + row;
            pa[i] = (gm < M) ? *(const uint4*)&A[(size_t)gm * 256 + u8 * 8]
                             : make_uint4(0u, 0u, 0u, 0u);
        }

#pragma unroll
        for (int kc = 0; kc < 4; kc++) {
            const int buf = kc & 1;
            const uint32_t aOff = OFF_A + (uint32_t)buf * 32768u;
            // store chunk: fp16 -> bf16 hi/lo images, swizzled (u8 = one 16B unit)
#pragma unroll
            for (int i = 0; i < 4; i++) {
                int p = i * 256 + tid, row = p >> 3, u8 = p & 7;
                uint4 v = pa[i];
                uint32_t hiw[4], low[4];
#pragma unroll
                for (int q = 0; q < 4; q++) {
                    uint32_t bits = (&v.x)[q];
                    float2 f = __half22float2(*(__half2*)&bits);
                    __nv_bfloat16 ha = __float2bfloat16_rn(f.x);
                    __nv_bfloat16 hb = __float2bfloat16_rn(f.y);
                    __nv_bfloat162 hp = __halves2bfloat162(ha, hb);
                    hiw[q] = *reinterpret_cast<uint32_t*>(&hp);
                    low[q] = bfpack(f.x - __bfloat162float(ha),
                                    f.y - __bfloat162float(hb));
                }
                uint32_t base = (uint32_t)row * 128u +
                                (uint32_t)((u8 ^ (row & 7)) << 4);
                *(uint4*)(smem + aOff + base) =
                    make_uint4(hiw[0], hiw[1], hiw[2], hiw[3]);
                *(uint4*)(smem + aOff + 16384u + base) =
                    make_uint4(low[0], low[1], low[2], low[3]);
            }
            __syncthreads();

            if (kc < 3) {
#pragma unroll
                for (int i = 0; i < 4; i++) {
                    int p = i * 256 + tid, row = p >> 3, u8 = p & 7, gm = m0 + row;
                    pa[i] = (gm < M)
                        ? *(const uint4*)&A[(size_t)gm * 256 + (kc + 1) * 64 + u8 * 8]
                        : make_uint4(0u, 0u, 0u, 0u);
                }
            }

            const uint32_t aH = sb + aOff;
            const uint32_t aL = aH + 16384u;
            const uint32_t bH = sb + (uint32_t)kc * (NF * 128u);
            const uint32_t bL = bH + (uint32_t)WIMG;
#pragma unroll
            for (int k16 = 0; k16 < 4; k16++) {
                uint32_t ah[2][4], al[2][4];
#pragma unroll
                for (int mt = 0; mt < 2; mt++) {
                    int row = wm * 32 + mt * 16 + r15;
                    uint32_t off = (uint32_t)row * 128u +
                                   (uint32_t)(((k16 * 2 + rh) ^ (row & 7)) << 4);
                    ldmatrix_x4(ah[mt], aH + off);
                    ldmatrix_x4(al[mt], aL + off);
                }
#pragma unroll
                for (int nt = 0; nt < NT; nt++) {
                    int rn = wnb + nt * 8 + (lane & 7);
                    int un = k16 * 2 + ((lane >> 3) & 1);
                    uint32_t off = (uint32_t)rn * 128u +
                                   (uint32_t)((un ^ (rn & 7)) << 4);
                    uint32_t bh[2], bl[2];
                    ldmatrix_x2(bh, bH + off);
                    ldmatrix_x2(bl, bL + off);
#pragma unroll
                    for (int mt = 0; mt < 2; mt++) {
                        mma16816(acc[mt][nt], ah[mt], bh);
                        mma16816(acc[mt][nt], ah[mt], bl);
                        mma16816(acc[mt][nt], al[mt], bh);
                    }
                }
            }
            __syncthreads();
        }

#pragma unroll
        for (int nt = 0; nt < NT; nt++) {
            int col = wnb + nt * 8 + (lane & 3) * 2;
            float bx = bias[col], by = bias[col + 1];
#pragma unroll
            for (int mt = 0; mt < 2; mt++) {
                int row = m0 + wm * 32 + mt * 16 + (lane >> 2);
                if (row < M) {
                    float2 o = make_float2(acc[mt][nt][0] + bx, acc[mt][nt][1] + by);
                    *(float2*)&C[(size_t)row * NF + col] = o;
                }
                if (row + 8 < M) {
                    float2 o = make_float2(acc[mt][nt][2] + bx, acc[mt][nt][3] + by);
                    *(float2*)&C[(size_t)(row + 8) * NF + col] = o;
                }
            }
        }
    }
}

// ---------------- launch ----------------
extern "C" void kernel_launch(void* const* d_in, const int* in_sizes, int n_in,
                              void* d_out, int out_size) {
    const float* x    = (const float*)d_in[0];
    const int*   eic  = (const int*)d_in[1];
    const int*   eil  = (const int*)d_in[2];
    const float* W1   = (const float*)d_in[3];
    const float* as1  = (const float*)d_in[4];
    const float* ad1  = (const float*)d_in[5];
    const float* b1   = (const float*)d_in[6];
    const float* W2   = (const float*)d_in[7];
    const float* as2  = (const float*)d_in[8];
    const float* ad2  = (const float*)d_in[9];
    const float* b2   = (const float*)d_in[10];
    const float* fcW  = (const float*)d_in[11];
    const float* fcb  = (const float*)d_in[12];
    float* out = (float*)d_out;

    __half *h1, *h2, *xcomb;
    float *pas1, *pad1, *pas2, *pad2;
    int *cnt, *offs, *cur, *csr;
    uint4* xs;
    __nv_bfloat16 *w1, *w2, *wf;
    cudaGetSymbolAddress((void**)&h1, g_h1);
    cudaGetSymbolAddress((void**)&h2, g_h2);
    cudaGetSymbolAddress((void**)&xcomb, g_xcomb);
    cudaGetSymbolAddress((void**)&pas1, g_as1);
    cudaGetSymbolAddress((void**)&pad1, g_ad1);
    cudaGetSymbolAddress((void**)&pas2, g_as2);
    cudaGetSymbolAddress((void**)&pad2, g_ad2);
    cudaGetSymbolAddress((void**)&cnt, g_cnt);
    cudaGetSymbolAddress((void**)&offs, g_offs);
    cudaGetSymbolAddress((void**)&cur, g_cur);
    cudaGetSymbolAddress((void**)&csr, g_csr);
    cudaGetSymbolAddress((void**)&xs, g_xs);
    cudaGetSymbolAddress((void**)&w1, g_w1);
    cudaGetSymbolAddress((void**)&w2, g_w2);
    cudaGetSymbolAddress((void**)&wf, g_wf);

    constexpr int SMEM_H = 131072 + 65536;   // 196608
    constexpr int SMEM_F = 65536 + 65536;    // 131072
    cudaFuncSetAttribute(gemm_h_kernel,
                         cudaFuncAttributeMaxDynamicSharedMemorySize, SMEM_H);
    cudaFuncSetAttribute(gemm_fc_kernel,
                         cudaFuncAttributeMaxDynamicSharedMemorySize, SMEM_F);

    // 1. zero counters
    cudaMemsetAsync(cnt, 0, 2 * NN * sizeof(int));

    // 2. phase1: pre-split x + count edges + prep weights
    phase1_kernel<<<PX_BLOCKS + CNT_BLOCKS + PW_BLOCKS, 256>>>(
        x, eic, eil, W1, W2, fcW, xs, w1, w2, wf, cnt);

    // 3. scan
    scan2_kernel<<<2, 1024>>>(cnt, offs, cur);

    // 4. both h-GEMMs in one launch
    gemm_h_kernel<<<148, 256, SMEM_H>>>(xs, w1, w2, h1, h2);

    // 5. fill CSR + attention coefficients
    phase3_kernel<<<FILL_BLOCKS + CNT_BLOCKS, 256>>>(eic, eil, cur, csr, h1, h2,
                                                     as1, ad1, as2, ad2,
                                                     pas1, pad1, pas2, pad2);

    // 6. aggregation (both layers, 2-edge unrolled, fp16 out)
    agg2_kernel<<<25000, 256>>>(h1, h2, pas1, pad1, pas2, pad2,
                                offs, csr, b1, b2, xcomb);

    // 7. final FC (fp16 input)
    gemm_fc_kernel<<<148, 256, SMEM_F>>>(xcomb, wf, fcb, out, NN, NTILES);
}

// round 17
// speedup vs baseline: 1.0413x; 1.0030x over previous
#include <cuda_runtime.h>
#include <cuda_bf16.h>
#include <cuda_fp16.h>
#include <cstdint>

#define NN 100000
#define EE 1600000
#define NTILES 782          // ceil(NN/128)

// ---------------- scratch (no allocation allowed) ----------------
__device__ __half g_h1[NN * 128];
__device__ __half g_h2[NN * 128];
__device__ __half g_xcomb[NN * 256];
__device__ float  g_as1[NN * 2];
__device__ float  g_ad1[NN * 2];
__device__ float  g_as2[NN * 2];
__device__ float  g_ad2[NN * 2];
__device__ int    g_cnt[2 * NN];
__device__ int    g_offs[2 * (NN + 1)];
__device__ int    g_cur[2 * NN];
__device__ int    g_csr[2 * EE];
// pre-split, pre-swizzled x images: per tile, per 64-k chunk: hi 16KB + lo 16KB
__device__ uint4  g_xs[NTILES * 8192];
// W^T bf16 hi image + lo image (swizzled, chunk-major)
__device__ __align__(16) __nv_bfloat16 g_w1[128 * 512];
__device__ __align__(16) __nv_bfloat16 g_w2[128 * 512];
__device__ __align__(16) __nv_bfloat16 g_wf[64 * 512];

// ---------------- helpers ----------------
__device__ __forceinline__ uint32_t smem_to_u32(const void* p) {
    uint32_t a;
    asm("{ .reg .u64 t; cvta.to.shared.u64 t, %1; cvt.u32.u64 %0, t; }" : "=r"(a) : "l"(p));
    return a;
}
__device__ __forceinline__ void ldmatrix_x4(uint32_t* r, uint32_t addr) {
    asm volatile("ldmatrix.sync.aligned.m8n8.x4.shared.b16 {%0,%1,%2,%3}, [%4];"
        : "=r"(r[0]), "=r"(r[1]), "=r"(r[2]), "=r"(r[3]) : "r"(addr));
}
__device__ __forceinline__ void ldmatrix_x2(uint32_t* r, uint32_t addr) {
    asm volatile("ldmatrix.sync.aligned.m8n8.x2.shared.b16 {%0,%1}, [%2];"
        : "=r"(r[0]), "=r"(r[1]) : "r"(addr));
}
__device__ __forceinline__ void mma16816(float* c, const uint32_t* a, const uint32_t* b) {
    asm volatile(
        "mma.sync.aligned.m16n8k16.row.col.f32.bf16.bf16.f32 "
        "{%0,%1,%2,%3},{%4,%5,%6,%7},{%8,%9},{%0,%1,%2,%3};"
        : "+f"(c[0]), "+f"(c[1]), "+f"(c[2]), "+f"(c[3])
        : "r"(a[0]), "r"(a[1]), "r"(a[2]), "r"(a[3]), "r"(b[0]), "r"(b[1]));
}
__device__ __forceinline__ void cp_async16(uint32_t dst, const void* src) {
    asm volatile("cp.async.cg.shared.global [%0], [%1], 16;" :: "r"(dst), "l"(src));
}
#define CP_COMMIT() asm volatile("cp.async.commit_group;")
#define CP_WAIT(n)  asm volatile("cp.async.wait_group %0;" :: "n"(n))
__device__ __forceinline__ uint32_t bf2bits(__nv_bfloat162 v) {
    return *reinterpret_cast<uint32_t*>(&v);
}
__device__ __forceinline__ uint32_t bfpack(float a, float b) {
    __nv_bfloat162 t = __halves2bfloat162(__float2bfloat16_rn(a), __float2bfloat16_rn(b));
    return *reinterpret_cast<uint32_t*>(&t);
}
__device__ __forceinline__ uint32_t h2bits(__half2 v) {
    return *reinterpret_cast<uint32_t*>(&v);
}

// ================= phase1: prep_x + count + prep_w (fused) =================
#define PX_BLOCKS 12512     // 782*4*128*8 / 256
#define CNT_BLOCKS 12500    // 2*EE / 256
#define PW_BLOCKS 320       // 81920 / 256
#define FILL_BLOCKS 6250    // 2*EE / 512

__global__ __launch_bounds__(256) void phase1_kernel(
    const float* __restrict__ x,
    const int* __restrict__ eic, const int* __restrict__ eil,
    const float* __restrict__ W1, const float* __restrict__ W2,
    const float* __restrict__ Wf,
    uint4* __restrict__ xs,
    __nv_bfloat16* __restrict__ o1, __nv_bfloat16* __restrict__ o2,
    __nv_bfloat16* __restrict__ of,
    int* __restrict__ cnt)
{
    const int b = blockIdx.x, tid = threadIdx.x;
    if (b < PX_BLOCKS) {
        // ---- pre-split x into swizzled bf16 hi/lo tile images ----
        int id = b * 256 + tid;
        int u = id & 7, r = (id >> 3) & 127, kc = (id >> 10) & 3, tile = id >> 12;
        int gm = tile * 128 + r;
        float4 v0 = make_float4(0.f, 0.f, 0.f, 0.f), v1 = v0;
        if (gm < NN) {
            const float* src = &x[(size_t)gm * 256 + kc * 64 + u * 8];
            v0 = *(const float4*)src;
            v1 = *(const float4*)(src + 4);
        }
        float f[8] = {v0.x, v0.y, v0.z, v0.w, v1.x, v1.y, v1.z, v1.w};
        uint32_t hi[4], lo[4];
#pragma unroll
        for (int q = 0; q < 4; q++) {
            __nv_bfloat16 ha = __float2bfloat16_rn(f[2 * q]);
            __nv_bfloat16 hb = __float2bfloat16_rn(f[2 * q + 1]);
            __nv_bfloat162 hp = __halves2bfloat162(ha, hb);
            hi[q] = *reinterpret_cast<uint32_t*>(&hp);
            lo[q] = bfpack(f[2 * q] - __bfloat162float(ha),
                           f[2 * q + 1] - __bfloat162float(hb));
        }
        int unit = r * 8 + (u ^ (r & 7));
        uint4* base = xs + (size_t)tile * 8192 + kc * 2048;
        base[unit]        = make_uint4(hi[0], hi[1], hi[2], hi[3]);
        base[1024 + unit] = make_uint4(lo[0], lo[1], lo[2], lo[3]);
    } else if (b < PX_BLOCKS + CNT_BLOCKS) {
        // ---- count incoming edges (both layers) ----
        int j = (b - PX_BLOCKS) * 256 + tid;
        if (j < EE)          atomicAdd(&cnt[eic[EE + j]], 1);
        else                 atomicAdd(&cnt[NN + eil[EE + (j - EE)]], 1);
    } else {
        // ---- prep weights: hi/lo swizzled images ----
        int id = (b - PX_BLOCKS - CNT_BLOCKS) * 256 + tid;
        const float* W; __nv_bfloat16* o; int NF, li;
        if (id < 32768)      { W = W1; o = o1; NF = 128; li = id; }
        else if (id < 65536) { W = W2; o = o2; NF = 128; li = id - 32768; }
        else                 { W = Wf; o = of; NF = 64;  li = id - 65536; }
        int n = li % NF, k = li / NF;
        float v = W[li];
        __nv_bfloat16 hv = __float2bfloat16_rn(v);
        __nv_bfloat16 lv = __float2bfloat16_rn(v - __bfloat162float(hv));
        uint32_t off = (uint32_t)((k >> 6) * NF + n) * 128u
                     + (uint32_t)((((k & 63) >> 3) ^ (n & 7)) << 4)
                     + (uint32_t)(k & 7) * 2u;
        *(__nv_bfloat16*)((char*)o + off) = hv;
        *(__nv_bfloat16*)((char*)(o + NF * 256) + off) = lv;
    }
}

// ================= h-GEMM + embedded scan =================
// 148 CTAs total: blocks 0..145 do GEMM (73 CTAs per layer, strided tiles);
// blocks 146/147 run the per-layer exclusive scan concurrently (hidden).
__global__ __launch_bounds__(256) void gemm_h_kernel(
    const uint4* __restrict__ xs,
    const __nv_bfloat16* __restrict__ w1, const __nv_bfloat16* __restrict__ w2,
    __half* __restrict__ h1, __half* __restrict__ h2,
    const int* __restrict__ cntA, int* __restrict__ offsA, int* __restrict__ curA)
{
    constexpr int NT = 8;
    constexpr int OFF_A = 131072;         // after 2 W images (64KB each)

    extern __shared__ __align__(16) char smem[];
    const int tid = threadIdx.x;

    if (blockIdx.x >= 146) {
        // ---- embedded scan (one block per layer, 256 threads) ----
        const int L = blockIdx.x - 146;
        const int* cnt = cntA + L * NN;
        int* offs = offsA + L * (NN + 1);
        int* cur  = curA + L * NN;
        int* sums = (int*)smem;
        const int CH = (NN + 255) / 256;   // 391
        int base = tid * CH;
        int local = 0;
        for (int i = 0; i < CH; i++) {
            int idx = base + i;
            if (idx < NN) local += cnt[idx];
        }
        sums[tid] = local;
        __syncthreads();
#pragma unroll
        for (int off = 1; off < 256; off <<= 1) {
            int v = (tid >= off) ? sums[tid - off] : 0;
            __syncthreads();
            sums[tid] += v;
            __syncthreads();
        }
        int run = sums[tid] - local;
        for (int i = 0; i < CH; i++) {
            int idx = base + i;
            if (idx < NN) {
                offs[idx] = run;
                cur[idx] = run;
                run += cnt[idx];
            }
        }
        if (base < NN && base + CH >= NN) offs[NN] = run;
        return;
    }

    const uint32_t sb = smem_to_u32(smem);
    const int wid = tid >> 5, lane = tid & 31;
    const int wm = wid & 3, wn = wid >> 2;
    const int wnb = wn * 64;

    const int half_ = blockIdx.x & 1;
    const int cidx = blockIdx.x >> 1;     // 0..72
    const __nv_bfloat16* Wt = half_ ? w2 : w1;
    __half* H = half_ ? h2 : h1;

    // W images -> smem once
    for (int i = tid; i < 8192; i += 256)
        cp_async16(sb + (uint32_t)i * 16u, ((const uint4*)Wt) + i);
    CP_COMMIT();
    CP_WAIT(0);
    __syncthreads();

    const int r15 = lane & 15, rh = lane >> 4;

    auto issueA = [&](int tile, int kc, int buf) {
        uint32_t dst = sb + OFF_A + (uint32_t)buf * 32768u;
        const uint4* src = xs + (size_t)tile * 8192 + kc * 2048;
#pragma unroll
        for (int i = 0; i < 8; i++)
            cp_async16(dst + (uint32_t)(i * 256 + tid) * 16u, src + i * 256 + tid);
        CP_COMMIT();
    };

    auto mmaChunk = [&](int kc, int buf, float acc[2][NT][4]) {
        const uint32_t aH = sb + OFF_A + (uint32_t)buf * 32768u;
        const uint32_t aL = aH + 16384u;
        const uint32_t bH = sb + (uint32_t)kc * 16384u;
        const uint32_t bL = bH + 65536u;
#pragma unroll
        for (int k16 = 0; k16 < 4; k16++) {
            uint32_t ah[2][4], al[2][4];
#pragma unroll
            for (int mt = 0; mt < 2; mt++) {
                int row = wm * 32 + mt * 16 + r15;
                uint32_t off = (uint32_t)row * 128u +
                               (uint32_t)(((k16 * 2 + rh) ^ (row & 7)) << 4);
                ldmatrix_x4(ah[mt], aH + off);
                ldmatrix_x4(al[mt], aL + off);
            }
#pragma unroll
            for (int nt = 0; nt < NT; nt++) {
                int rn = wnb + nt * 8 + (lane & 7);
                int un = k16 * 2 + ((lane >> 3) & 1);
                uint32_t off = (uint32_t)rn * 128u + (uint32_t)((un ^ (rn & 7)) << 4);
                uint32_t bh[2], bl[2];
                ldmatrix_x2(bh, bH + off);
                ldmatrix_x2(bl, bL + off);
#pragma unroll
                for (int mt = 0; mt < 2; mt++) {
                    mma16816(acc[mt][nt], ah[mt], bh);
                    mma16816(acc[mt][nt], ah[mt], bl);
                    mma16816(acc[mt][nt], al[mt], bh);
                }
            }
        }
    };

    int tile = cidx;
    if (tile < NTILES) { issueA(tile, 0, 0); issueA(tile, 1, 1); }

    for (; tile < NTILES; tile += 73) {
        const int m0 = tile * 128;
        const int nxt = tile + 73;
        const bool hasNext = (nxt < NTILES);
        float acc[2][NT][4];
#pragma unroll
        for (int mt = 0; mt < 2; mt++)
#pragma unroll
            for (int nt = 0; nt < NT; nt++)
#pragma unroll
                for (int q = 0; q < 4; q++) acc[mt][nt][q] = 0.f;

        // kc = 0
        CP_WAIT(1); __syncthreads();
        mmaChunk(0, 0, acc); __syncthreads();
        issueA(tile, 2, 0);
        // kc = 1
        CP_WAIT(1); __syncthreads();
        mmaChunk(1, 1, acc); __syncthreads();
        issueA(tile, 3, 1);
        // kc = 2
        CP_WAIT(1); __syncthreads();
        mmaChunk(2, 0, acc); __syncthreads();
        if (hasNext) issueA(nxt, 0, 0);
        // kc = 3
        if (hasNext) { CP_WAIT(1); } else { CP_WAIT(0); }
        __syncthreads();
        mmaChunk(3, 1, acc); __syncthreads();
        if (hasNext) issueA(nxt, 1, 1);

        // epilogue: fp32 acc -> fp16 stores
#pragma unroll
        for (int nt = 0; nt < NT; nt++) {
            int col = wnb + nt * 8 + (lane & 3) * 2;
#pragma unroll
            for (int mt = 0; mt < 2; mt++) {
                int row = m0 + wm * 32 + mt * 16 + (lane >> 2);
                if (row < NN) {
                    __half2 v = __floats2half2_rn(acc[mt][nt][0], acc[mt][nt][1]);
                    *(__half2*)&H[(size_t)row * 128 + col] = v;
                }
                if (row + 8 < NN) {
                    __half2 v = __floats2half2_rn(acc[mt][nt][2], acc[mt][nt][3]);
                    *(__half2*)&H[(size_t)(row + 8) * 128 + col] = v;
                }
            }
        }
    }
}

// ================= phase3: fill CSR (2 edges/thread) + acoef (fused) =================
__global__ __launch_bounds__(256) void phase3_kernel(
    const int* __restrict__ eic, const int* __restrict__ eil,
    int* __restrict__ cur, int* __restrict__ csr,
    const __half* __restrict__ h1, const __half* __restrict__ h2,
    const float* __restrict__ as1, const float* __restrict__ ad1,
    const float* __restrict__ as2, const float* __restrict__ ad2,
    float* __restrict__ oas1, float* __restrict__ oad1,
    float* __restrict__ oas2, float* __restrict__ oad2)
{
    const int b = blockIdx.x, tid = threadIdx.x;
    if (b < FILL_BLOCKS) {
        int j0 = b * 512 + tid;
#pragma unroll
        for (int q = 0; q < 2; q++) {
            int j = j0 + q * 256;
            const int* ei; int* cu; int* cs; int e;
            if (j < EE) { ei = eic; cu = cur;      cs = csr;      e = j; }
            else        { ei = eil; cu = cur + NN; cs = csr + EE; e = j - EE; }
            int s = ei[e], d = ei[EE + e];
            int pos = atomicAdd(&cu[d], 1);
            cs[pos] = s;
        }
    } else {
        int node = ((b - FILL_BLOCKS) * 256 + tid) >> 5;
        if (node >= NN) return;
        int lane = tid & 31;
        int hl = lane >> 4;
#pragma unroll
        for (int L = 0; L < 2; L++) {
            const __half* h = (L == 0) ? h1 : h2;
            const float* ats = (L == 0) ? as1 : as2;
            const float* atd = (L == 0) ? ad1 : ad2;
            float* oas = (L == 0) ? oas1 : oas2;
            float* oad = (L == 0) ? oad1 : oad2;

            uint2 raw = *(const uint2*)&h[(size_t)node * 128 + lane * 4];
            float2 f0 = __half22float2(*(__half2*)&raw.x);
            float2 f1 = __half22float2(*(__half2*)&raw.y);
            float4 sv = *(const float4*)&ats[lane * 4];
            float4 dv = *(const float4*)&atd[lane * 4];
            float ps = f0.x * sv.x + f0.y * sv.y + f1.x * sv.z + f1.y * sv.w;
            float pd = f0.x * dv.x + f0.y * dv.y + f1.x * dv.z + f1.y * dv.w;
#pragma unroll
            for (int o = 8; o > 0; o >>= 1) {
                ps += __shfl_xor_sync(0xffffffffu, ps, o);
                pd += __shfl_xor_sync(0xffffffffu, pd, o);
            }
            if ((lane & 15) == 0) {
                oas[node * 2 + hl] = ps;
                oad[node * 2 + hl] = pd;
            }
        }
    }
}

// ================= aggregation: both layers, one warp per dst, 4-edge pipeline =====
__global__ __launch_bounds__(256) void agg2_kernel(
    const __half* __restrict__ h1, const __half* __restrict__ h2,
    const float* __restrict__ pas1, const float* __restrict__ pad1,
    const float* __restrict__ pas2, const float* __restrict__ pad2,
    const int* __restrict__ offsA, const int* __restrict__ csrA,
    const float* __restrict__ b1, const float* __restrict__ b2,
    __half* __restrict__ xcomb)
{
    int g = blockIdx.x * 8 + (threadIdx.x >> 5);
    int layer = (g >= NN);
    int node = g - layer * NN;
    int lane = threadIdx.x & 31;
    int hl = lane >> 4;
    int c4 = (lane & 15) * 4;

    const __half* h   = layer ? h2 : h1;
    const float* asrc = layer ? pas2 : pas1;
    const float* adst = layer ? pad2 : pad1;
    const int* offs   = offsA + layer * (NN + 1);
    const int* csr    = csrA + layer * EE;
    const float* bias = layer ? b2 : b1;
    const int colOff  = layer * 128;

    float ad = adst[node * 2 + hl];

    // self loop (analytic)
    float e = asrc[node * 2 + hl] + ad;
    e = (e > 0.f) ? e : 0.2f * e;
    float p = __expf(e);
    float sum = p;
    uint2 raw = *(const uint2*)&h[(size_t)node * 128 + hl * 64 + c4];
    float2 f0 = __half22float2(*(__half2*)&raw.x);
    float2 f1 = __half22float2(*(__half2*)&raw.y);
    float4 acc = make_float4(f0.x * p, f0.y * p, f1.x * p, f1.y * p);

    int beg = offs[node], end = offs[node + 1];
    int j = beg;
    // 4-edge software pipeline: issue all loads before consuming
    for (; j + 3 < end; j += 4) {
        int s0 = csr[j], s1 = csr[j + 1], s2 = csr[j + 2], s3 = csr[j + 3];
        float a0 = asrc[s0 * 2 + hl];
        float a1 = asrc[s1 * 2 + hl];
        float a2 = asrc[s2 * 2 + hl];
        float a3 = asrc[s3 * 2 + hl];
        uint2 r0 = *(const uint2*)&h[(size_t)s0 * 128 + hl * 64 + c4];
        uint2 r1 = *(const uint2*)&h[(size_t)s1 * 128 + hl * 64 + c4];
        uint2 r2 = *(const uint2*)&h[(size_t)s2 * 128 + hl * 64 + c4];
        uint2 r3 = *(const uint2*)&h[(size_t)s3 * 128 + hl * 64 + c4];
        float e0 = a0 + ad; e0 = (e0 > 0.f) ? e0 : 0.2f * e0;
        float e1 = a1 + ad; e1 = (e1 > 0.f) ? e1 : 0.2f * e1;
        float e2 = a2 + ad; e2 = (e2 > 0.f) ? e2 : 0.2f * e2;
        float e3 = a3 + ad; e3 = (e3 > 0.f) ? e3 : 0.2f * e3;
        float p0 = __expf(e0), p1 = __expf(e1), p2 = __expf(e2), p3 = __expf(e3);
        sum += (p0 + p1) + (p2 + p3);
        float2 q0 = __half22float2(*(__half2*)&r0.x);
        float2 q1 = __half22float2(*(__half2*)&r0.y);
        float2 q2 = __half22float2(*(__half2*)&r1.x);
        float2 q3 = __half22float2(*(__half2*)&r1.y);
        float2 q4 = __half22float2(*(__half2*)&r2.x);
        float2 q5 = __half22float2(*(__half2*)&r2.y);
        float2 q6 = __half22float2(*(__half2*)&r3.x);
        float2 q7 = __half22float2(*(__half2*)&r3.y);
        acc.x = fmaf(q0.x, p0, fmaf(q2.x, p1, fmaf(q4.x, p2, fmaf(q6.x, p3, acc.x))));
        acc.y = fmaf(q0.y, p0, fmaf(q2.y, p1, fmaf(q4.y, p2, fmaf(q6.y, p3, acc.y))));
        acc.z = fmaf(q1.x, p0, fmaf(q3.x, p1, fmaf(q5.x, p2, fmaf(q7.x, p3, acc.z))));
        acc.w = fmaf(q1.y, p0, fmaf(q3.y, p1, fmaf(q5.y, p2, fmaf(q7.y, p3, acc.w))));
    }
    for (; j < end; j++) {
        int s = csr[j];
        float e2 = asrc[s * 2 + hl] + ad;
        e2 = (e2 > 0.f) ? e2 : 0.2f * e2;
        float p2 = __expf(e2);
        sum += p2;
        uint2 r2 = *(const uint2*)&h[(size_t)s * 128 + hl * 64 + c4];
        float2 g0 = __half22float2(*(__half2*)&r2.x);
        float2 g1 = __half22float2(*(__half2*)&r2.y);
        acc.x = fmaf(g0.x, p2, acc.x);
        acc.y = fmaf(g0.y, p2, acc.y);
        acc.z = fmaf(g1.x, p2, acc.z);
        acc.w = fmaf(g1.y, p2, acc.w);
    }

    float inv = 1.f / sum;
    float4 bv = *(const float4*)&bias[hl * 64 + c4];
    float rx = fmaxf(fmaf(acc.x, inv, bv.x), 0.f);
    float ry = fmaxf(fmaf(acc.y, inv, bv.y), 0.f);
    float rz = fmaxf(fmaf(acc.z, inv, bv.z), 0.f);
    float rw = fmaxf(fmaf(acc.w, inv, bv.w), 0.f);
    uint2 st;
    st.x = h2bits(__floats2half2_rn(rx, ry));
    st.y = h2bits(__floats2half2_rn(rz, rw));
    *(uint2*)&xcomb[(size_t)node * 256 + colOff + hl * 64 + c4] = st;
}

// ================= FC GEMM (fp16 A, inline bf16 hi/lo split, NF=64) =================
__global__ __launch_bounds__(256) void gemm_fc_kernel(
    const __half* __restrict__ A, const __nv_bfloat16* __restrict__ Wt,
    const float* __restrict__ bias, float* __restrict__ C, int M, int numTiles)
{
    constexpr int NF = 64, NT = 4;
    constexpr int WIMG = NF * 512;       // 32768
    constexpr int OFF_A = 2 * WIMG;      // 65536

    extern __shared__ __align__(16) char smem[];
    const uint32_t sb = smem_to_u32(smem);
    const int tid = threadIdx.x, wid = tid >> 5, lane = tid & 31;
    const int wm = wid & 3, wn = wid >> 2;
    const int wnb = wn * 32;

    for (int i = tid; i < NF * 64; i += 256)
        cp_async16(sb + (uint32_t)i * 16u, ((const uint4*)Wt) + i);
    CP_COMMIT();
    CP_WAIT(0);
    __syncthreads();

    const int r15 = lane & 15, rh = lane >> 4;
    uint4 pa[4];

    for (int tile = blockIdx.x; tile < numTiles; tile += gridDim.x) {
        const int m0 = tile * 128;
        float acc[2][NT][4];
#pragma unroll
        for (int mt = 0; mt < 2; mt++)
#pragma unroll
            for (int nt = 0; nt < NT; nt++)
#pragma unroll
                for (int q = 0; q < 4; q++) acc[mt][nt][q] = 0.f;

#pragma unroll
        for (int i = 0; i < 4; i++) {
            int p = i * 256 + tid, row = p >> 3, u8 = p & 7, gm = m0 + row;
            pa[i] = (gm < M) ? *(const uint4*)&A[(size_t)gm * 256 + u8 * 8]
                             : make_uint4(0u, 0u, 0u, 0u);
        }

#pragma unroll
        for (int kc = 0; kc < 4; kc++) {
            const int buf = kc & 1;
            const uint32_t aOff = OFF_A + (uint32_t)buf * 32768u;
#pragma unroll
            for (int i = 0; i < 4; i++) {
                int p = i * 256 + tid, row = p >> 3, u8 = p & 7;
                uint4 v = pa[i];
                uint32_t hiw[4], low[4];
#pragma unroll
                for (int q = 0; q < 4; q++) {
                    uint32_t bits = (&v.x)[q];
                    float2 f = __half22float2(*(__half2*)&bits);
                    __nv_bfloat16 ha = __float2bfloat16_rn(f.x);
                    __nv_bfloat16 hb = __float2bfloat16_rn(f.y);
                    __nv_bfloat162 hp = __halves2bfloat162(ha, hb);
                    hiw[q] = *reinterpret_cast<uint32_t*>(&hp);
                    low[q] = bfpack(f.x - __bfloat162float(ha),
                                    f.y - __bfloat162float(hb));
                }
                uint32_t base = (uint32_t)row * 128u +
                                (uint32_t)((u8 ^ (row & 7)) << 4);
                *(uint4*)(smem + aOff + base) =
                    make_uint4(hiw[0], hiw[1], hiw[2], hiw[3]);
                *(uint4*)(smem + aOff + 16384u + base) =
                    make_uint4(low[0], low[1], low[2], low[3]);
            }
            __syncthreads();

            if (kc < 3) {
#pragma unroll
                for (int i = 0; i < 4; i++) {
                    int p = i * 256 + tid, row = p >> 3, u8 = p & 7, gm = m0 + row;
                    pa[i] = (gm < M)
                        ? *(const uint4*)&A[(size_t)gm * 256 + (kc + 1) * 64 + u8 * 8]
                        : make_uint4(0u, 0u, 0u, 0u);
                }
            }

            const uint32_t aH = sb + aOff;
            const uint32_t aL = aH + 16384u;
            const uint32_t bH = sb + (uint32_t)kc * (NF * 128u);
            const uint32_t bL = bH + (uint32_t)WIMG;
#pragma unroll
            for (int k16 = 0; k16 < 4; k16++) {
                uint32_t ah[2][4], al[2][4];
#pragma unroll
                for (int mt = 0; mt < 2; mt++) {
                    int row = wm * 32 + mt * 16 + r15;
                    uint32_t off = (uint32_t)row * 128u +
                                   (uint32_t)(((k16 * 2 + rh) ^ (row & 7)) << 4);
                    ldmatrix_x4(ah[mt], aH + off);
                    ldmatrix_x4(al[mt], aL + off);
                }
#pragma unroll
                for (int nt = 0; nt < NT; nt++) {
                    int rn = wnb + nt * 8 + (lane & 7);
                    int un = k16 * 2 + ((lane >> 3) & 1);
                    uint32_t off = (uint32_t)rn * 128u +
                                   (uint32_t)((un ^ (rn & 7)) << 4);
                    uint32_t bh[2], bl[2];
                    ldmatrix_x2(bh, bH + off);
                    ldmatrix_x2(bl, bL + off);
#pragma unroll
                    for (int mt = 0; mt < 2; mt++) {
                        mma16816(acc[mt][nt], ah[mt], bh);
                        mma16816(acc[mt][nt], ah[mt], bl);
                        mma16816(acc[mt][nt], al[mt], bh);
                    }
                }
            }
            __syncthreads();
        }

#pragma unroll
        for (int nt = 0; nt < NT; nt++) {
            int col = wnb + nt * 8 + (lane & 3) * 2;
            float bx = bias[col], by = bias[col + 1];
#pragma unroll
            for (int mt = 0; mt < 2; mt++) {
                int row = m0 + wm * 32 + mt * 16 + (lane >> 2);
                if (row < M) {
                    float2 o = make_float2(acc[mt][nt][0] + bx, acc[mt][nt][1] + by);
                    *(float2*)&C[(size_t)row * NF + col] = o;
                }
                if (row + 8 < M) {
                    float2 o = make_float2(acc[mt][nt][2] + bx, acc[mt][nt][3] + by);
                    *(float2*)&C[(size_t)(row + 8) * NF + col] = o;
                }
            }
        }
    }
}

// ---------------- launch ----------------
extern "C" void kernel_launch(void* const* d_in, const int* in_sizes, int n_in,
                              void* d_out, int out_size) {
    const float* x    = (const float*)d_in[0];
    const int*   eic  = (const int*)d_in[1];
    const int*   eil  = (const int*)d_in[2];
    const float* W1   = (const float*)d_in[3];
    const float* as1  = (const float*)d_in[4];
    const float* ad1  = (const float*)d_in[5];
    const float* b1   = (const float*)d_in[6];
    const float* W2   = (const float*)d_in[7];
    const float* as2  = (const float*)d_in[8];
    const float* ad2  = (const float*)d_in[9];
    const float* b2   = (const float*)d_in[10];
    const float* fcW  = (const float*)d_in[11];
    const float* fcb  = (const float*)d_in[12];
    float* out = (float*)d_out;

    __half *h1, *h2, *xcomb;
    float *pas1, *pad1, *pas2, *pad2;
    int *cnt, *offs, *cur, *csr;
    uint4* xs;
    __nv_bfloat16 *w1, *w2, *wf;
    cudaGetSymbolAddress((void**)&h1, g_h1);
    cudaGetSymbolAddress((void**)&h2, g_h2);
    cudaGetSymbolAddress((void**)&xcomb, g_xcomb);
    cudaGetSymbolAddress((void**)&pas1, g_as1);
    cudaGetSymbolAddress((void**)&pad1, g_ad1);
    cudaGetSymbolAddress((void**)&pas2, g_as2);
    cudaGetSymbolAddress((void**)&pad2, g_ad2);
    cudaGetSymbolAddress((void**)&cnt, g_cnt);
    cudaGetSymbolAddress((void**)&offs, g_offs);
    cudaGetSymbolAddress((void**)&cur, g_cur);
    cudaGetSymbolAddress((void**)&csr, g_csr);
    cudaGetSymbolAddress((void**)&xs, g_xs);
    cudaGetSymbolAddress((void**)&w1, g_w1);
    cudaGetSymbolAddress((void**)&w2, g_w2);
    cudaGetSymbolAddress((void**)&wf, g_wf);

    constexpr int SMEM_H = 131072 + 65536;   // 196608
    constexpr int SMEM_F = 65536 + 65536;    // 131072
    cudaFuncSetAttribute(gemm_h_kernel,
                         cudaFuncAttributeMaxDynamicSharedMemorySize, SMEM_H);
    cudaFuncSetAttribute(gemm_fc_kernel,
                         cudaFuncAttributeMaxDynamicSharedMemorySize, SMEM_F);

    // 1. zero counters
    cudaMemsetAsync(cnt, 0, 2 * NN * sizeof(int));

    // 2. phase1: pre-split x + count edges + prep weights
    phase1_kernel<<<PX_BLOCKS + CNT_BLOCKS + PW_BLOCKS, 256>>>(
        x, eic, eil, W1, W2, fcW, xs, w1, w2, wf, cnt);

    // 3. both h-GEMMs + embedded scan in one launch (scan hidden under GEMM)
    gemm_h_kernel<<<148, 256, SMEM_H>>>(xs, w1, w2, h1, h2, cnt, offs, cur);

    // 4. fill CSR + attention coefficients
    phase3_kernel<<<FILL_BLOCKS + CNT_BLOCKS, 256>>>(eic, eil, cur, csr, h1, h2,
                                                     as1, ad1, as2, ad2,
                                                     pas1, pad1, pas2, pad2);

    // 5. aggregation (both layers, 4-edge pipelined, fp16 out)
    agg2_kernel<<<25000, 256>>>(h1, h2, pas1, pad1, pas2, pad2,
                                offs, csr, b1, b2, xcomb);

    // 6. final FC (fp16 input)
    gemm_fc_kernel<<<148, 256, SMEM_F>>>(xcomb, wf, fcb, out, NN, NTILES);
}